// round 1
// baseline (speedup 1.0000x reference)
#include <cuda_runtime.h>
#include <math.h>

#define ROWS     512
#define NBASIS   256
#define RGRID    1024
#define QS       2048
#define NSLOTS   128
#define COLS_IN  512
#define SLOT_ELEMS (ROWS * RGRID)          // 524288
#define SLOT4      (SLOT_ELEMS / 4)        // 131072 = 2^17

// K = sqrt(0.5 * log2(e)) / H,  H = 0.1
#define KSCALE   8.49321999f
// 1 / (B * H * sqrt(2*pi)) = 1 / (256 * 0.1 * 2.5066282746)
#define INV_NORM 0.0155836865f

__device__ float g_stats[ROWS * 4];   // smin, smax, ymin, ymax per row

__device__ __forceinline__ float fwd_y(float s, int sl) {
    switch (sl) {
        case 0: return 2.0f * s;
        case 1: return s - 3.0f;
        case 2: { float ss = (fabsf(s) < 1e-6f) ? 1e-6f : s; return 1.0f / ss; }
        case 3: return 0.8f * s + 5.0f;
        case 4: {
            if (s >= 0.0f) { float e = expf(-s); return 1.0f / (1.0f + e); }
            else           { float e = expf(s);  return e / (1.0f + e); }
        }
        default: // softplus, stable form
            return fmaxf(s, 0.0f) + log1pf(expf(-fabsf(s)));
    }
}

__global__ __launch_bounds__(256) void stats_kernel(
    const float* __restrict__ inputs,
    const float* __restrict__ noise,
    const int*   __restrict__ comp_idx,
    const int*   __restrict__ sel)
{
    __shared__ float xs[NBASIS];
    __shared__ float red[4][8];
    int r = blockIdx.x;
    int t = threadIdx.x;

    xs[t] = inputs[t * COLS_IN + r];
    __syncthreads();

    int sl = sel[r];
    float smn =  INFINITY, smx = -INFINITY;
    float ymn =  INFINITY, ymx = -INFINITY;

    const float* nzr = noise    + (size_t)r * QS;
    const int*   cir = comp_idx + (size_t)r * QS;

    for (int q = t; q < QS; q += 256) {
        float sv = xs[cir[q]] + 0.1f * nzr[q];
        smn = fminf(smn, sv);  smx = fmaxf(smx, sv);
        float y = fwd_y(sv, sl);
        ymn = fminf(ymn, y);   ymx = fmaxf(ymx, y);
    }

    #pragma unroll
    for (int o = 16; o > 0; o >>= 1) {
        smn = fminf(smn, __shfl_xor_sync(0xffffffffu, smn, o));
        smx = fmaxf(smx, __shfl_xor_sync(0xffffffffu, smx, o));
        ymn = fminf(ymn, __shfl_xor_sync(0xffffffffu, ymn, o));
        ymx = fmaxf(ymx, __shfl_xor_sync(0xffffffffu, ymx, o));
    }
    int w = t >> 5;
    if ((t & 31) == 0) { red[0][w] = smn; red[1][w] = smx; red[2][w] = ymn; red[3][w] = ymx; }
    __syncthreads();
    if (t == 0) {
        float a = red[0][0], b = red[1][0], c = red[2][0], d = red[3][0];
        #pragma unroll
        for (int i = 1; i < 8; i++) {
            a = fminf(a, red[0][i]); b = fmaxf(b, red[1][i]);
            c = fminf(c, red[2][i]); d = fmaxf(d, red[3][i]);
        }
        g_stats[r * 4 + 0] = a; g_stats[r * 4 + 1] = b;
        g_stats[r * 4 + 2] = c; g_stats[r * 4 + 3] = d;
    }
}

__device__ __forceinline__ float ex2f_raw(float a) {
    float r;
    asm("ex2.approx.ftz.f32 %0, %1;" : "=f"(r) : "f"(a));
    return r;
}

// Even blocks: pdf compute for (row, type). Odd blocks: bank->out copy.
__global__ __launch_bounds__(256) void main_kernel(
    const float* __restrict__ inputs,
    const float* __restrict__ bank,
    const int*   __restrict__ sel,
    const int*   __restrict__ slot_p,
    float*       __restrict__ out)
{
    int slot_idx = slot_p ? __ldg(slot_p) : 37;
    int bid = blockIdx.x;
    int t   = threadIdx.x;

    if ((bid & 1) == 0) {
        // ---------- compute branch ----------
        int cid  = bid >> 1;        // 0..1023
        int row  = cid >> 1;        // 0..511
        int type = cid & 1;         // 0 = current, 1 = transformed

        __shared__ float xsK[NBASIS];
        xsK[t] = inputs[t * COLS_IN + row] * KSCALE;
        __syncthreads();

        float mn   = g_stats[row * 4 + type * 2 + 0];
        float mx   = g_stats[row * 4 + type * 2 + 1];
        float span = mx - mn;
        int sl = (type == 1) ? sel[row] : -1;

        float u[4], lf[4];
        #pragma unroll
        for (int i = 0; i < 4; i++) {
            int j = t + i * 256;
            float frac = (float)j / 1023.0f;
            float tg = mn + span * frac;
            if (tg == 0.0f) tg = 1e-7f;
            float xi, l;
            if (type == 0) { xi = tg; l = 1.0f; }
            else {
                switch (sl) {
                    case 0: xi = tg * 0.5f;          l = 0.5f;  break;
                    case 1: xi = tg + 3.0f;          l = 1.0f;  break;
                    case 2: xi = 1.0f / tg;          l = 1.0f / (tg * tg); break;
                    case 3: xi = (tg - 5.0f) / 0.8f; l = 1.25f; break;
                    case 4: {
                        float yc = fminf(fmaxf(tg, 1e-6f), 1.0f - 1e-6f);
                        xi = logf(yc) - log1pf(-yc);
                        l  = 1.0f / (yc * (1.0f - yc));
                        break;
                    }
                    default: {
                        float yp = fmaxf(tg, 1e-6f);
                        float em = expm1f(yp);
                        xi = logf(em);
                        l  = 1.0f / (-expm1f(-yp));
                        break;
                    }
                }
            }
            u[i]  = xi * KSCALE;
            lf[i] = l;
        }

        float a0 = 0.f, a1 = 0.f, a2 = 0.f, a3 = 0.f;
        #pragma unroll 8
        for (int b = 0; b < NBASIS; b++) {
            float xv = xsK[b];
            float d0 = u[0] - xv;
            float d1 = u[1] - xv;
            float d2 = u[2] - xv;
            float d3 = u[3] - xv;
            a0 += ex2f_raw(-d0 * d0);
            a1 += ex2f_raw(-d1 * d1);
            a2 += ex2f_raw(-d2 * d2);
            a3 += ex2f_raw(-d3 * d3);
        }

        if (slot_idx != type) {
            float* dst = out + (size_t)type * SLOT_ELEMS + (size_t)row * RGRID;
            float v0 = (a0 == 0.f) ? 0.f : a0 * INV_NORM * lf[0];
            float v1 = (a1 == 0.f) ? 0.f : a1 * INV_NORM * lf[1];
            float v2 = (a2 == 0.f) ? 0.f : a2 * INV_NORM * lf[2];
            float v3 = (a3 == 0.f) ? 0.f : a3 * INV_NORM * lf[3];
            dst[t]       = v0;
            dst[t + 256] = v1;
            dst[t + 512] = v2;
            dst[t + 768] = v3;
        }
    } else {
        // ---------- copy branch ----------
        int cb = bid >> 1;          // 0..1023
        const float4* src4 = (const float4*)bank;
        float4*       dst4 = (float4*)out;
        const long total4 = (long)NSLOTS * SLOT4;   // 16,777,216
        const long stride = 1024L * 256L;
        for (long idx = (long)cb * 256 + t; idx < total4; idx += stride) {
            int  s   = (int)(idx >> 17);        // slot (SLOT4 = 2^17)
            long off = idx & (long)(SLOT4 - 1);
            int  srcs;
            if (s == slot_idx)      srcs = 0;   // out[slot_idx] = prev = bank[0]
            else if (s < 2)         continue;   // slots 0/1 written by compute blocks
            else                    srcs = s;
            dst4[idx] = src4[(long)srcs * SLOT4 + off];
        }
    }
}

extern "C" void kernel_launch(void* const* d_in, const int* in_sizes, int n_in,
                              void* d_out, int out_size)
{
    const float* inputs   = (const float*)d_in[0];
    const float* bank     = (const float*)d_in[1];
    const float* noise    = (const float*)d_in[2];
    const int*   comp_idx = (const int*)  d_in[3];
    const int*   sel      = (const int*)  d_in[4];
    const int*   slot_p   = (n_in >= 6) ? (const int*)d_in[5] : nullptr;
    float* out = (float*)d_out;

    stats_kernel<<<ROWS, 256>>>(inputs, noise, comp_idx, sel);
    main_kernel<<<2048, 256>>>(inputs, bank, sel, slot_p, out);
}